// round 2
// baseline (speedup 1.0000x reference)
#include <cuda_runtime.h>

// ---------------------------------------------------------------------------
// SSIM (5x5 Gaussian, sigma=1.5, SAME zero padding), fused single kernel.
// Separable convolution + f32x2 packed math + register rolling row window.
// ---------------------------------------------------------------------------

constexpr int W    = 512;
constexpr int H    = 512;
constexpr int C    = 3;
constexpr int NB   = 16;
constexpr int BX   = 128;   // output columns per block (4 warps x 32)
constexpr int ROWS = 32;    // output rows per block

__device__ __forceinline__ unsigned long long pk2(float lo, float hi) {
    unsigned long long r;
    asm("mov.b64 %0, {%1, %2};" : "=l"(r) : "f"(lo), "f"(hi));
    return r;
}
__device__ __forceinline__ void up2(unsigned long long v, float& lo, float& hi) {
    asm("mov.b64 {%0, %1}, %2;" : "=f"(lo), "=f"(hi) : "l"(v));
}
__device__ __forceinline__ unsigned long long fma2_(unsigned long long a,
                                                    unsigned long long b,
                                                    unsigned long long c) {
    unsigned long long d;
    asm("fma.rn.f32x2 %0, %1, %2, %3;" : "=l"(d) : "l"(a), "l"(b), "l"(c));
    return d;
}
__device__ __forceinline__ unsigned long long mul2_(unsigned long long a,
                                                    unsigned long long b) {
    unsigned long long d;
    asm("mul.rn.f32x2 %0, %1, %2;" : "=l"(d) : "l"(a), "l"(b));
    return d;
}

__global__ __launch_bounds__(128)
void ssim_kernel(const float* __restrict__ img1,
                 const float* __restrict__ img2,
                 const float* __restrict__ win,
                 float* __restrict__ out)
{
    // Per-warp row buffer: 36 (a,b) pairs per channel.
    __shared__ float2 buf[4][C][36];

    const int lane = threadIdx.x & 31;
    const int warp = threadIdx.x >> 5;
    const int b    = blockIdx.z;
    const int y0   = blockIdx.y * ROWS;            // first output row
    const int x0   = blockIdx.x * BX + warp * 32;  // first output col of strip
    const int xo   = x0 + lane;                    // this thread's output col
    const int gx   = x0 - 2 + lane;                // halo load col (36 wide)
    const int gx2  = x0 + 30 + lane;               // extra halo col (lane<4)

    // Recover separable 1D Gaussian from the 2D window input:
    // w2d[i][j] = g[i]*g[j]  =>  g[j] = w2d[2][j] / sqrt(w2d[2][2])
    const float gc = sqrtf(win[12]);
    float g[5];
    unsigned long long wg[5];
#pragma unroll
    for (int j = 0; j < 5; ++j) {
        g[j]  = __fdividef(win[10 + j], gc);
        wg[j] = pk2(g[j], g[j]);
    }

    const bool gxok  = (gx >= 0) && (gx < W);
    const bool gx2ok = (lane < 4) && (gx2 < W);

    // Per-channel base offsets for row 0 of this image/channel.
    int cbase[C];
#pragma unroll
    for (int c = 0; c < C; ++c) cbase[c] = ((b * C + c) * H) * W;

    // Rolling horizontal-filtered state: 5 row slots per channel.
    // hAB: packed (sum_a, sum_b); hSQ: packed (sum_a2, sum_b2); hX: sum_ab.
    unsigned long long hAB[C][5], hSQ[C][5];
    float hX[C][5];

    const float C1 = 0.0001f;  // (0.01)^2
    const float C2 = 0.0009f;  // (0.03)^2

    // Steps s = 0..ROWS+3 over input rows r = y0-2+s. Slot = s % 5 (static
    // after the inner unroll since base % 5 == 0).
    for (int base = 0; base < ROWS + 8; base += 5) {
#pragma unroll
        for (int k = 0; k < 5; ++k) {
            const int s = base + k;
            if (s < ROWS + 4) {
                const int r = y0 - 2 + s;           // input row (may be OOB)
                const bool rok = (r >= 0) && (r < H);
                const int roff = r * W;

                __syncwarp();
                if (rok) {
#pragma unroll
                    for (int c = 0; c < C; ++c) {
                        const int off = cbase[c] + roff;
                        float a0 = gxok ? img1[off + gx] : 0.0f;
                        float b0 = gxok ? img2[off + gx] : 0.0f;
                        buf[warp][c][lane] = make_float2(a0, b0);
                        if (lane < 4) {
                            float a1 = gx2ok ? img1[off + gx2] : 0.0f;
                            float b1 = gx2ok ? img2[off + gx2] : 0.0f;
                            buf[warp][c][32 + lane] = make_float2(a1, b1);
                        }
                    }
                }
                __syncwarp();

                // Horizontal 5-tap pass into slot k.
#pragma unroll
                for (int c = 0; c < C; ++c) {
                    if (rok) {
                        unsigned long long sab = 0ull, ssq = 0ull;
                        float sx = 0.0f;
#pragma unroll
                        for (int t = 0; t < 5; ++t) {
                            float2 p = buf[warp][c][lane + t];
                            unsigned long long pp = pk2(p.x, p.y);
                            sab = fma2_(pp, wg[t], sab);               // a, b
                            ssq = fma2_(mul2_(pp, pp), wg[t], ssq);    // a2, b2
                            sx  = fmaf(p.x * p.y, g[t], sx);           // ab
                        }
                        hAB[c][k] = sab; hSQ[c][k] = ssq; hX[c][k] = sx;
                    } else {
                        hAB[c][k] = 0ull; hSQ[c][k] = 0ull; hX[c][k] = 0.0f;
                    }
                }

                // Vertical 5-tap pass + SSIM epilogue for output row y = r-2.
                if (s >= 4) {
                    float acc = 0.0f;
#pragma unroll
                    for (int c = 0; c < C; ++c) {
                        unsigned long long vab = 0ull, vsq = 0ull;
                        float vx = 0.0f;
#pragma unroll
                        for (int j = 0; j < 5; ++j) {
                            const int slot = (k + 1 + j) % 5;  // row r-4+j
                            vab = fma2_(hAB[c][slot], wg[j], vab);
                            vsq = fma2_(hSQ[c][slot], wg[j], vsq);
                            vx  = fmaf(hX[c][slot], g[j], vx);
                        }
                        float mu1, mu2, saa, sbb;
                        up2(vab, mu1, mu2);
                        up2(vsq, saa, sbb);
                        const float m11 = mu1 * mu1;
                        const float m22 = mu2 * mu2;
                        const float m12 = mu1 * mu2;
                        const float s11 = saa - m11;
                        const float s22 = sbb - m22;
                        const float s12 = vx  - m12;
                        const float num = (2.0f * m12 + C1) * (2.0f * s12 + C2);
                        const float den = (m11 + m22 + C1) * (s11 + s22 + C2);
                        acc += __fdividef(num, den);
                    }
                    const int y = y0 + s - 4;
                    out[(b * H + y) * W + xo] = acc * (1.0f / 3.0f);
                }
            }
        }
    }
}

extern "C" void kernel_launch(void* const* d_in, const int* in_sizes, int n_in,
                              void* d_out, int out_size)
{
    const float* img1 = (const float*)d_in[0];
    const float* img2 = (const float*)d_in[1];
    const float* win  = (const float*)d_in[2];
    float* out = (float*)d_out;

    dim3 grid(W / BX, H / ROWS, NB);  // (4, 16, 16) = 1024 blocks
    ssim_kernel<<<grid, 128>>>(img1, img2, win, out);
}

// round 4
// speedup vs baseline: 2.0000x; 2.0000x over previous
#include <cuda_runtime.h>

// ---------------------------------------------------------------------------
// SSIM (5x5 Gaussian, sigma=1.5, SAME zero padding), fused single kernel.
// Separable conv + f32x2 packed math + register rolling window +
// one-row software-pipelined global prefetch.
// ---------------------------------------------------------------------------

constexpr int W    = 512;
constexpr int H    = 512;
constexpr int C    = 3;
constexpr int NB   = 16;
constexpr int BX   = 128;   // output columns per block (4 warps x 32)
constexpr int ROWS = 32;    // output rows per block

__device__ __forceinline__ unsigned long long pk2(float lo, float hi) {
    unsigned long long r;
    asm("mov.b64 %0, {%1, %2};" : "=l"(r) : "f"(lo), "f"(hi));
    return r;
}
__device__ __forceinline__ void up2(unsigned long long v, float& lo, float& hi) {
    asm("mov.b64 {%0, %1}, %2;" : "=f"(lo), "=f"(hi) : "l"(v));
}
__device__ __forceinline__ unsigned long long fma2_(unsigned long long a,
                                                    unsigned long long b,
                                                    unsigned long long c) {
    unsigned long long d;
    asm("fma.rn.f32x2 %0, %1, %2, %3;" : "=l"(d) : "l"(a), "l"(b), "l"(c));
    return d;
}

__global__ __launch_bounds__(128)
void ssim_kernel(const float* __restrict__ img1,
                 const float* __restrict__ img2,
                 const float* __restrict__ win,
                 float* __restrict__ out)
{
    // Per-warp row buffers (36 cols = 32 + 4 halo), products precomputed.
    __shared__ float2 sAB[4][C][36];   // (a, b)
    __shared__ float2 sSQ[4][C][36];   // (a*a, b*b)
    __shared__ float  sX [4][C][36];   // a*b

    const int lane = threadIdx.x & 31;
    const int warp = threadIdx.x >> 5;
    const int b    = blockIdx.z;
    const int y0   = blockIdx.y * ROWS;
    const int x0   = blockIdx.x * BX + warp * 32;
    const int xo   = x0 + lane;
    const int gx   = x0 - 2 + lane;       // main halo col
    const int gx2  = x0 + 30 + lane;      // extra halo col (lane<4)

    // Recover separable 1D Gaussian: g[j] = w2d[2][j] / sqrt(w2d[2][2])
    const float gc = sqrtf(win[12]);
    float g[5];
    unsigned long long wg[5];
#pragma unroll
    for (int j = 0; j < 5; ++j) {
        g[j]  = __fdividef(win[10 + j], gc);
        wg[j] = pk2(g[j], g[j]);
    }

    const bool gxok  = (gx >= 0) && (gx < W);
    const bool gx2ok = (lane < 4) && (gx2 < W);

    int cbase[C];
#pragma unroll
    for (int c = 0; c < C; ++c) cbase[c] = ((b * C + c) * H) * W;

    // Rolling horizontal-filtered state: 5 row slots per channel.
    unsigned long long hAB[C][5], hSQ[C][5];
    float hX[C][5];

    // Prefetch registers (row s, loaded one iteration ahead).
    float pa[C], pb[C], qa[C], qb[C];

    // Prologue: prefetch row s=0 (r = y0-2).
    {
        const int r = y0 - 2;
        const bool rok = (r >= 0);
        const int rclamp = (rok ? r : 0) * W;   // safe offset even when OOB
        float ta[C], tb[C], ua[C], ub[C];
#pragma unroll
        for (int c = 0; c < C; ++c) {
            const int off = cbase[c] + rclamp;
            ta[c] = gxok  ? img1[off + gx]  : 0.0f;
            tb[c] = gxok  ? img2[off + gx]  : 0.0f;
            ua[c] = gx2ok ? img1[off + gx2] : 0.0f;
            ub[c] = gx2ok ? img2[off + gx2] : 0.0f;
        }
#pragma unroll
        for (int c = 0; c < C; ++c) {
            pa[c] = rok ? ta[c] : 0.0f;
            pb[c] = rok ? tb[c] : 0.0f;
            qa[c] = rok ? ua[c] : 0.0f;
            qb[c] = rok ? ub[c] : 0.0f;
        }
    }

    const float C1 = 0.0001f;  // (0.01)^2
    const float C2 = 0.0009f;  // (0.03)^2

    for (int base = 0; base < ROWS + 8; base += 5) {
#pragma unroll
        for (int k = 0; k < 5; ++k) {
            const int s = base + k;
            if (s < ROWS + 4) {
                // ---- store prefetched row s to smem (products precomputed) ----
                __syncwarp();
#pragma unroll
                for (int c = 0; c < C; ++c) {
                    const float a = pa[c], bb = pb[c];
                    sAB[warp][c][lane] = make_float2(a, bb);
                    sSQ[warp][c][lane] = make_float2(a * a, bb * bb);
                    sX [warp][c][lane] = a * bb;
                    if (lane < 4) {
                        const float a1 = qa[c], b1 = qb[c];
                        sAB[warp][c][32 + lane] = make_float2(a1, b1);
                        sSQ[warp][c][32 + lane] = make_float2(a1 * a1, b1 * b1);
                        sX [warp][c][32 + lane] = a1 * b1;
                    }
                }
                __syncwarp();

                // ---- prefetch row s+1 (consumed next iteration; hidden
                //      behind the compute below). Loads grouped first for MLP. ----
                {
                    const int r = y0 - 1 + s;          // (y0-2) + (s+1)
                    const bool rok = (r >= 0) && (r < H);
                    const int rclamp = (rok ? r : 0) * W;
                    float ta[C], tb[C], ua[C], ub[C];
#pragma unroll
                    for (int c = 0; c < C; ++c) {
                        const int off = cbase[c] + rclamp;
                        ta[c] = gxok  ? img1[off + gx]  : 0.0f;
                        tb[c] = gxok  ? img2[off + gx]  : 0.0f;
                        ua[c] = gx2ok ? img1[off + gx2] : 0.0f;
                        ub[c] = gx2ok ? img2[off + gx2] : 0.0f;
                    }
#pragma unroll
                    for (int c = 0; c < C; ++c) {
                        pa[c] = rok ? ta[c] : 0.0f;
                        pb[c] = rok ? tb[c] : 0.0f;
                        qa[c] = rok ? ua[c] : 0.0f;
                        qb[c] = rok ? ub[c] : 0.0f;
                    }
                }

                // ---- horizontal 5-tap pass into slot k (branch-free) ----
#pragma unroll
                for (int c = 0; c < C; ++c) {
                    const unsigned long long* pAB =
                        (const unsigned long long*)&sAB[warp][c][0];
                    const unsigned long long* pSQ =
                        (const unsigned long long*)&sSQ[warp][c][0];
                    const float* pX = &sX[warp][c][0];
                    unsigned long long sab = 0ull, ssq = 0ull;
                    float sx = 0.0f;
#pragma unroll
                    for (int t = 0; t < 5; ++t) {
                        sab = fma2_(pAB[lane + t], wg[t], sab);
                        ssq = fma2_(pSQ[lane + t], wg[t], ssq);
                        sx  = fmaf(pX[lane + t], g[t], sx);
                    }
                    hAB[c][k] = sab; hSQ[c][k] = ssq; hX[c][k] = sx;
                }

                // ---- vertical 5-tap pass + epilogue for row y = s-4+y0 ----
                if (s >= 4) {
                    float num[C], den[C];
#pragma unroll
                    for (int c = 0; c < C; ++c) {
                        unsigned long long vab = 0ull, vsq = 0ull;
                        float vx = 0.0f;
#pragma unroll
                        for (int j = 0; j < 5; ++j) {
                            const int slot = (k + 1 + j) % 5;  // row s-4+j
                            vab = fma2_(hAB[c][slot], wg[j], vab);
                            vsq = fma2_(hSQ[c][slot], wg[j], vsq);
                            vx  = fmaf(hX[c][slot], g[j], vx);
                        }
                        float mu1, mu2, saa, sbb;
                        up2(vab, mu1, mu2);
                        up2(vsq, saa, sbb);
                        const float m11 = mu1 * mu1;
                        const float m22 = mu2 * mu2;
                        const float m12 = mu1 * mu2;
                        const float s12 = vx - m12;
                        num[c] = (2.0f * m12 + C1) * (2.0f * s12 + C2);
                        den[c] = (m11 + m22 + C1) *
                                 ((saa - m11) + (sbb - m22) + C2);
                    }
                    // Sum of 3 ratios with a single division.
                    const float d01   = den[0] * den[1];
                    const float denom = d01 * den[2];
                    float numer = num[2] * d01;
                    numer = fmaf(num[0], den[1] * den[2], numer);
                    numer = fmaf(num[1], den[0] * den[2], numer);
                    const int y = y0 + s - 4;
                    out[(b * H + y) * W + xo] =
                        __fdividef(numer, denom) * (1.0f / 3.0f);
                }
            }
        }
    }
}

extern "C" void kernel_launch(void* const* d_in, const int* in_sizes, int n_in,
                              void* d_out, int out_size)
{
    const float* img1 = (const float*)d_in[0];
    const float* img2 = (const float*)d_in[1];
    const float* win  = (const float*)d_in[2];
    float* out = (float*)d_out;

    dim3 grid(W / BX, H / ROWS, NB);  // (4, 16, 16) = 1024 blocks
    ssim_kernel<<<grid, 128>>>(img1, img2, win, out);
}

// round 5
// speedup vs baseline: 2.8401x; 1.4201x over previous
#include <cuda_runtime.h>

// ---------------------------------------------------------------------------
// SSIM (5x5 Gaussian, sigma=1.5, SAME zero padding), fused single kernel.
// Separable conv + f32x2 packed math + register rolling window +
// one-row software-pipelined global prefetch.
// R5: smem holds raw (a,b) only; squares/cross recomputed in registers
//     (cuts L1/LDS traffic 3x, which R4 showed was the binding pipe).
// ---------------------------------------------------------------------------

constexpr int W    = 512;
constexpr int H    = 512;
constexpr int C    = 3;
constexpr int NB   = 16;
constexpr int BX   = 128;   // output columns per block (4 warps x 32)
constexpr int ROWS = 32;    // output rows per block

__device__ __forceinline__ unsigned long long pk2(float lo, float hi) {
    unsigned long long r;
    asm("mov.b64 %0, {%1, %2};" : "=l"(r) : "f"(lo), "f"(hi));
    return r;
}
__device__ __forceinline__ void up2(unsigned long long v, float& lo, float& hi) {
    asm("mov.b64 {%0, %1}, %2;" : "=f"(lo), "=f"(hi) : "l"(v));
}
__device__ __forceinline__ unsigned long long fma2_(unsigned long long a,
                                                    unsigned long long b,
                                                    unsigned long long c) {
    unsigned long long d;
    asm("fma.rn.f32x2 %0, %1, %2, %3;" : "=l"(d) : "l"(a), "l"(b), "l"(c));
    return d;
}
__device__ __forceinline__ unsigned long long mul2_(unsigned long long a,
                                                    unsigned long long b) {
    unsigned long long d;
    asm("mul.rn.f32x2 %0, %1, %2;" : "=l"(d) : "l"(a), "l"(b));
    return d;
}

__global__ __launch_bounds__(128)
void ssim_kernel(const float* __restrict__ img1,
                 const float* __restrict__ img2,
                 const float* __restrict__ win,
                 float* __restrict__ out)
{
    // Per-warp row buffer (36 cols = 32 + 4 halo): raw (a,b) pairs only.
    __shared__ float2 sAB[4][C][36];

    const int lane = threadIdx.x & 31;
    const int warp = threadIdx.x >> 5;
    const int b    = blockIdx.z;
    const int y0   = blockIdx.y * ROWS;
    const int x0   = blockIdx.x * BX + warp * 32;
    const int xo   = x0 + lane;
    const int gx   = x0 - 2 + lane;       // main halo col
    const int gx2  = x0 + 30 + lane;      // extra halo col (lane<4)

    // Recover separable 1D Gaussian: g[j] = w2d[2][j] / sqrt(w2d[2][2])
    const float gc = sqrtf(win[12]);
    float g[5];
    unsigned long long wg[5];
#pragma unroll
    for (int j = 0; j < 5; ++j) {
        g[j]  = __fdividef(win[10 + j], gc);
        wg[j] = pk2(g[j], g[j]);
    }

    const bool gxok  = (gx >= 0) && (gx < W);
    const bool gx2ok = (lane < 4) && (gx2 < W);

    int cbase[C];
#pragma unroll
    for (int c = 0; c < C; ++c) cbase[c] = ((b * C + c) * H) * W;

    // Rolling horizontal-filtered state: 5 row slots per channel.
    unsigned long long hAB[C][5], hSQ[C][5];
    float hX[C][5];

    // Prefetch registers (row s, loaded one iteration ahead).
    float pa[C], pb[C], qa[C], qb[C];

    // Prologue: prefetch row s=0 (r = y0-2).
    {
        const int r = y0 - 2;
        const bool rok = (r >= 0);
        const int rclamp = (rok ? r : 0) * W;   // safe offset even when OOB
        float ta[C], tb[C], ua[C], ub[C];
#pragma unroll
        for (int c = 0; c < C; ++c) {
            const int off = cbase[c] + rclamp;
            ta[c] = gxok  ? img1[off + gx]  : 0.0f;
            tb[c] = gxok  ? img2[off + gx]  : 0.0f;
            ua[c] = gx2ok ? img1[off + gx2] : 0.0f;
            ub[c] = gx2ok ? img2[off + gx2] : 0.0f;
        }
#pragma unroll
        for (int c = 0; c < C; ++c) {
            pa[c] = rok ? ta[c] : 0.0f;
            pb[c] = rok ? tb[c] : 0.0f;
            qa[c] = rok ? ua[c] : 0.0f;
            qb[c] = rok ? ub[c] : 0.0f;
        }
    }

    const float C1 = 0.0001f;  // (0.01)^2
    const float C2 = 0.0009f;  // (0.03)^2

    for (int base = 0; base < ROWS + 8; base += 5) {
#pragma unroll
        for (int k = 0; k < 5; ++k) {
            const int s = base + k;
            if (s < ROWS + 4) {
                // ---- store prefetched row s to smem (raw pairs only) ----
                __syncwarp();
#pragma unroll
                for (int c = 0; c < C; ++c) {
                    sAB[warp][c][lane] = make_float2(pa[c], pb[c]);
                    if (lane < 4)
                        sAB[warp][c][32 + lane] = make_float2(qa[c], qb[c]);
                }
                __syncwarp();

                // ---- prefetch row s+1 (consumed next iteration; hidden
                //      behind the compute below). Loads grouped for MLP. ----
                {
                    const int r = y0 - 1 + s;          // (y0-2) + (s+1)
                    const bool rok = (r >= 0) && (r < H);
                    const int rclamp = (rok ? r : 0) * W;
                    float ta[C], tb[C], ua[C], ub[C];
#pragma unroll
                    for (int c = 0; c < C; ++c) {
                        const int off = cbase[c] + rclamp;
                        ta[c] = gxok  ? img1[off + gx]  : 0.0f;
                        tb[c] = gxok  ? img2[off + gx]  : 0.0f;
                        ua[c] = gx2ok ? img1[off + gx2] : 0.0f;
                        ub[c] = gx2ok ? img2[off + gx2] : 0.0f;
                    }
#pragma unroll
                    for (int c = 0; c < C; ++c) {
                        pa[c] = rok ? ta[c] : 0.0f;
                        pb[c] = rok ? tb[c] : 0.0f;
                        qa[c] = rok ? ua[c] : 0.0f;
                        qb[c] = rok ? ub[c] : 0.0f;
                    }
                }

                // ---- horizontal 5-tap pass into slot k ----
                // Squares/cross recomputed in regs: 1 LDS.64 per tap only.
#pragma unroll
                for (int c = 0; c < C; ++c) {
                    const unsigned long long* pAB =
                        (const unsigned long long*)&sAB[warp][c][0];
                    unsigned long long sab = 0ull, ssq = 0ull;
                    float sx = 0.0f;
#pragma unroll
                    for (int t = 0; t < 5; ++t) {
                        const unsigned long long pp = pAB[lane + t];
                        float ax, bx;
                        up2(pp, ax, bx);                          // free (reg pair)
                        sab = fma2_(pp, wg[t], sab);              // a, b
                        ssq = fma2_(mul2_(pp, pp), wg[t], ssq);   // a2, b2
                        sx  = fmaf(ax * bx, g[t], sx);            // ab
                    }
                    hAB[c][k] = sab; hSQ[c][k] = ssq; hX[c][k] = sx;
                }

                // ---- vertical 5-tap pass + epilogue for row y = s-4+y0 ----
                if (s >= 4) {
                    float num[C], den[C];
#pragma unroll
                    for (int c = 0; c < C; ++c) {
                        unsigned long long vab = 0ull, vsq = 0ull;
                        float vx = 0.0f;
#pragma unroll
                        for (int j = 0; j < 5; ++j) {
                            const int slot = (k + 1 + j) % 5;  // row s-4+j
                            vab = fma2_(hAB[c][slot], wg[j], vab);
                            vsq = fma2_(hSQ[c][slot], wg[j], vsq);
                            vx  = fmaf(hX[c][slot], g[j], vx);
                        }
                        float mu1, mu2, saa, sbb;
                        up2(vab, mu1, mu2);
                        up2(vsq, saa, sbb);
                        const float m11 = mu1 * mu1;
                        const float m22 = mu2 * mu2;
                        const float m12 = mu1 * mu2;
                        const float s12 = vx - m12;
                        num[c] = (2.0f * m12 + C1) * (2.0f * s12 + C2);
                        den[c] = (m11 + m22 + C1) *
                                 ((saa - m11) + (sbb - m22) + C2);
                    }
                    // Sum of 3 ratios with a single division.
                    const float d01   = den[0] * den[1];
                    const float denom = d01 * den[2];
                    float numer = num[2] * d01;
                    numer = fmaf(num[0], den[1] * den[2], numer);
                    numer = fmaf(num[1], den[0] * den[2], numer);
                    const int y = y0 + s - 4;
                    out[(b * H + y) * W + xo] =
                        __fdividef(numer, denom) * (1.0f / 3.0f);
                }
            }
        }
    }
}

extern "C" void kernel_launch(void* const* d_in, const int* in_sizes, int n_in,
                              void* d_out, int out_size)
{
    const float* img1 = (const float*)d_in[0];
    const float* img2 = (const float*)d_in[1];
    const float* win  = (const float*)d_in[2];
    float* out = (float*)d_out;

    dim3 grid(W / BX, H / ROWS, NB);  // (4, 16, 16) = 1024 blocks
    ssim_kernel<<<grid, 128>>>(img1, img2, win, out);
}